// round 2
// baseline (speedup 1.0000x reference)
#include <cuda_runtime.h>

#define N_G 256
#define D 1024
#define D4 (D / 4)
#define KSPLIT 8
#define KSLICE (D / KSPLIT)   // 128

#define BM 64
#define BN 64
#define BK 16

// Static device scratch (allocation-free rule)
__device__ float g_A[N_G * D];                 // group-mean of im rows (scaled 1/nc)
__device__ float g_B[N_G * D];                 // group-mean of s  rows (scaled 1/ncap)
__device__ float g_diag[N_G];
__device__ float g_Sp[KSPLIT][N_G * N_G];      // split-K partial S

// ---------------------------------------------------------------------------
// K1: segmented row sums, scaled by 1/count. Blocks 0..255 -> im groups,
//     256..511 -> s groups. 256 threads, each owns one float4 column slot.
// ---------------------------------------------------------------------------
__global__ __launch_bounds__(256)
void k_groupsum(const float* __restrict__ im, const float* __restrict__ s,
                const int* __restrict__ ncl, const int* __restrict__ nca,
                float* __restrict__ out) {
    __shared__ int scnt[N_G];
    __shared__ int soff;

    int b = blockIdx.x;
    bool isB = (b >= N_G);
    int g = isB ? b - N_G : b;
    const int* cnts = isB ? nca : ncl;
    int t = threadIdx.x;

    scnt[t] = cnts[t];                 // coalesced; avoid serial LDG scan
    if (b == 0 && t == 0) out[0] = 0.f;
    __syncthreads();
    if (t == 0) {
        int o = 0;
        for (int k = 0; k < g; k++) o += scnt[k];   // LDS scan, cheap
        soff = o;
    }
    __syncthreads();

    int off = soff, cnt = scnt[g];
    const float4* src = (const float4*)(isB ? s : im);
    src += (long)off * D4 + t;

    float4 acc = make_float4(0.f, 0.f, 0.f, 0.f);
    for (int r = 0; r < cnt; r++) {
        float4 v = src[(long)r * D4];
        acc.x += v.x; acc.y += v.y; acc.z += v.z; acc.w += v.w;
    }
    float inv = 1.f / (float)cnt;
    acc.x *= inv; acc.y *= inv; acc.z *= inv; acc.w *= inv;

    float4* dst = (float4*)(isB ? g_B : g_A);
    dst[g * D4 + t] = acc;
}

// ---------------------------------------------------------------------------
// K2: split-K GEMM  S_partial[kz] = A[:, kz-slice] @ B[:, kz-slice]^T
//     grid (4,4,8), 256 threads, 64x64 tile, 4x4 micro per thread.
// ---------------------------------------------------------------------------
__global__ __launch_bounds__(256)
void k_gemm() {
    __shared__ float As[BK][BM];
    __shared__ float Bs[BK][BN];

    int ib = blockIdx.x, jb = blockIdx.y, kz = blockIdx.z;
    int tid = threadIdx.x;
    int tx = tid & 15;          // output col group
    int ty = tid >> 4;          // output row group
    int lm = tid & 63;          // load: row within tile
    int lk = (tid >> 6) << 2;   // load: k offset {0,4,8,12}

    const float4* Ag = (const float4*)g_A;
    const float4* Bg = (const float4*)g_B;

    float acc[4][4] = {};

    int k0base = kz * KSLICE;
    for (int kc = 0; kc < KSLICE; kc += BK) {
        int kq = (k0base + kc + lk) >> 2;
        float4 av = Ag[(ib * BM + lm) * D4 + kq];
        float4 bv = Bg[(jb * BN + lm) * D4 + kq];
        __syncthreads();
        As[lk + 0][lm] = av.x; As[lk + 1][lm] = av.y;
        As[lk + 2][lm] = av.z; As[lk + 3][lm] = av.w;
        Bs[lk + 0][lm] = bv.x; Bs[lk + 1][lm] = bv.y;
        Bs[lk + 2][lm] = bv.z; Bs[lk + 3][lm] = bv.w;
        __syncthreads();

#pragma unroll
        for (int kk = 0; kk < BK; kk++) {
            float4 a4 = *(const float4*)&As[kk][ty << 2];
            float4 b4 = *(const float4*)&Bs[kk][tx << 2];
            acc[0][0] += a4.x * b4.x; acc[0][1] += a4.x * b4.y;
            acc[0][2] += a4.x * b4.z; acc[0][3] += a4.x * b4.w;
            acc[1][0] += a4.y * b4.x; acc[1][1] += a4.y * b4.y;
            acc[1][2] += a4.y * b4.z; acc[1][3] += a4.y * b4.w;
            acc[2][0] += a4.z * b4.x; acc[2][1] += a4.z * b4.y;
            acc[2][2] += a4.z * b4.z; acc[2][3] += a4.z * b4.w;
            acc[3][0] += a4.w * b4.x; acc[3][1] += a4.w * b4.y;
            acc[3][2] += a4.w * b4.z; acc[3][3] += a4.w * b4.w;
        }
    }

    float* Sp = g_Sp[kz];
#pragma unroll
    for (int r = 0; r < 4; r++) {
        int i = ib * BM + (ty << 2) + r;
        float4 v = make_float4(acc[r][0], acc[r][1], acc[r][2], acc[r][3]);
        *(float4*)&Sp[i * N_G + jb * BN + (tx << 2)] = v;
    }
}

// ---------------------------------------------------------------------------
// K3: diag[i] = sum_z Sp[z][i,i]   (counts already folded into A/B)
// ---------------------------------------------------------------------------
__global__ void k_diag() {
    int i = threadIdx.x;
    float d = 0.f;
#pragma unroll
    for (int z = 0; z < KSPLIT; z++) d += g_Sp[z][i * N_G + i];
    g_diag[i] = d;
}

// ---------------------------------------------------------------------------
// K4: loss = sum_{i!=j} max(S_ij - diag_i, 0) + max(S_ij - diag_j, 0)
//     grid 64 blocks x 256 thr; each thread 4 contiguous-coalesced entries.
// ---------------------------------------------------------------------------
__global__ __launch_bounds__(256)
void k_loss(float* __restrict__ out) {
    int base = blockIdx.x * 1024 + threadIdx.x;
    float sum = 0.f;
#pragma unroll
    for (int u = 0; u < 4; u++) {
        int idx = base + u * 256;
        int i = idx >> 8, j = idx & 255;
        float sv = 0.f;
#pragma unroll
        for (int z = 0; z < KSPLIT; z++) sv += g_Sp[z][idx];
        if (i != j)
            sum += fmaxf(sv - g_diag[i], 0.f) + fmaxf(sv - g_diag[j], 0.f);
    }
    __shared__ float red[256];
    red[threadIdx.x] = sum;
    __syncthreads();
    for (int st = 128; st > 0; st >>= 1) {
        if (threadIdx.x < st) red[threadIdx.x] += red[threadIdx.x + st];
        __syncthreads();
    }
    if (threadIdx.x == 0) atomicAdd(out, red[0]);
}

// ---------------------------------------------------------------------------
extern "C" void kernel_launch(void* const* d_in, const int* in_sizes, int n_in,
                              void* d_out, int out_size) {
    const float* im  = (const float*)d_in[0];
    const float* s   = (const float*)d_in[1];
    const int*   ncl = (const int*)d_in[2];
    const int*   nca = (const int*)d_in[3];
    float* out = (float*)d_out;

    k_groupsum<<<2 * N_G, 256>>>(im, s, ncl, nca, out);
    dim3 g2(N_G / BM, N_G / BN, KSPLIT);
    k_gemm<<<g2, 256>>>();
    k_diag<<<1, N_G>>>();
    k_loss<<<64, 256>>>(out);
}